// round 14
// baseline (speedup 1.0000x reference)
#include <cuda_runtime.h>

// DAVIS346 voxelization constants
#define CW 346
#define CH 260
#define CC 16
#define NUM_VOX  (2 * CC * CH * CW)   // 2,877,440 floats
#define NUM_VOX4 (NUM_VOX / 4)        // 719,360 float4
#define EV_PER_THREAD 2
#define TPB 256
#define ZC 148                        // zeroing CTAs = bids 0..147 (all in wave 1)

// Device-global sync state (data, not allocation). Reset each launch by the
// last-exiting CTA, so CUDA-graph replays are deterministic.
__device__ unsigned g_zero_done = 0;  // zero-CTAs that finished their slice
__device__ unsigned g_exit_cnt  = 0;  // CTAs that finished everything

__global__ __launch_bounds__(TPB)
void vox_fused_kernel(const float4* __restrict__ ev,
                      float* __restrict__ out, int n) {
    const int bid  = blockIdx.x;
    const int tid  = threadIdx.x;
    const int base = bid * (TPB * EV_PER_THREAD) + tid;
    const unsigned Z = (gridDim.x < ZC) ? gridDim.x : ZC;

    // Front-issue the two event loads (proven MLP=2 optimum) — they fly while
    // the zero phase / flag wait proceeds.
    float4 e0 = (base < n)       ? __ldcs(&ev[base])       : make_float4(0.f, 0.f, -1.f, 0.f);
    float4 e1 = (base + TPB < n) ? __ldcs(&ev[base + TPB]) : make_float4(0.f, 0.f, -1.f, 0.f);

    // ---- Inline zero phase: bids 0..Z-1 clear the poisoned output ----
    if ((unsigned)bid < Z) {
        float4* out4 = (float4*)out;
        const float4 z4 = make_float4(0.f, 0.f, 0.f, 0.f);
        for (int i = bid * TPB + tid; i < NUM_VOX4; i += (int)Z * TPB)
            out4[i] = z4;
        __threadfence();                 // release: zero stores visible
        __syncthreads();                 // whole CTA done zeroing
        if (tid == 0) atomicAdd(&g_zero_done, 1u);
    }

    // ---- Index math (overlaps the wait) ----
    // idx = x + 346*y + 346*260*((ceil(16t)-1) + 16*(p>0)); exact in fp32 (<2^24)
    float fb0 = ceilf(e0.z * (float)CC) - 1.0f + ((e0.w > 0.0f) ? (float)CC : 0.0f);
    float fb1 = ceilf(e1.z * (float)CC) - 1.0f + ((e1.w > 0.0f) ? (float)CC : 0.0f);
    int idx0 = (int)fmaf((float)(CW * CH), fb0, fmaf((float)CW, e0.y, e0.x));
    int idx1 = (int)fmaf((float)(CW * CH), fb1, fmaf((float)CW, e1.y, e1.x));
    bool v0 = (e0.z > 0.0f) && (e0.z <= 1.0f);
    bool v1 = (e1.z > 0.0f) && (e1.z <= 1.0f);

    // ---- Wait until all zeroing is complete (thread 0 polls, others park) ----
    if (tid == 0) {
        while (*(volatile unsigned*)&g_zero_done < Z) __nanosleep(64);
    }
    __syncthreads();
    __threadfence();                     // acquire before our scatter stores

    if (v0) out[idx0] = 1.0f;            // non-accumulating scatter, races benign
    if (v1) out[idx1] = 1.0f;

    // ---- Reset sync state for the next graph replay (last CTA out) ----
    __syncthreads();
    if (tid == 0) {
        __threadfence();                 // our stores before the exit count
        unsigned p = atomicAdd(&g_exit_cnt, 1u);
        if (p == gridDim.x - 1u) {       // we are the last CTA: safe to reset
            g_zero_done = 0u;
            __threadfence();
            g_exit_cnt = 0u;
        }
    }
}

extern "C" void kernel_launch(void* const* d_in, const int* in_sizes, int n_in,
                              void* d_out, int out_size) {
    const float4* ev = (const float4*)d_in[0];
    float* out = (float*)d_out;
    int n = in_sizes[0] / 4;              // events are [N,4] float32

    int blocks = (n + TPB * EV_PER_THREAD - 1) / (TPB * EV_PER_THREAD);
    vox_fused_kernel<<<blocks, TPB>>>(ev, out, n);
}

// round 15
// speedup vs baseline: 1.9299x; 1.9299x over previous
#include <cuda_runtime.h>

// DAVIS346 voxelization constants
#define CW 346
#define CH 260
#define CC 16
#define NUM_VOX (2 * CC * CH * CW)   // 2,877,440 floats
#define EV_PER_THREAD 2
#define TPB 256

__global__ __launch_bounds__(TPB)
void vox_scatter_kernel(const float4* __restrict__ ev,
                        float* __restrict__ out, int n) {
    int base = blockIdx.x * (TPB * EV_PER_THREAD) + threadIdx.x;

    // Two independent streaming loads (MLP=2) — measured optimum across the
    // EV={1,2,4,8} x TPB={256,512} sweep (covers latency without flooding L1tex).
    float4 e0 = (base < n)       ? __ldcs(&ev[base])       : make_float4(0.f, 0.f, -1.f, 0.f);
    float4 e1 = (base + TPB < n) ? __ldcs(&ev[base + TPB]) : make_float4(0.f, 0.f, -1.f, 0.f);

    // idx = x + 346*y + 346*260*((ceil(16t)-1) + 16*(p>0)); exact in fp32 (<2^24)
    float fb0 = ceilf(e0.z * (float)CC) - 1.0f + ((e0.w > 0.0f) ? (float)CC : 0.0f);
    float fb1 = ceilf(e1.z * (float)CC) - 1.0f + ((e1.w > 0.0f) ? (float)CC : 0.0f);
    int idx0 = (int)fmaf((float)(CW * CH), fb0, fmaf((float)CW, e0.y, e0.x));
    int idx1 = (int)fmaf((float)(CW * CH), fb1, fmaf((float)CW, e1.y, e1.x));
    bool v0 = (e0.z > 0.0f) && (e0.z <= 1.0f);
    bool v1 = (e1.z > 0.0f) && (e1.z <= 1.0f);

    // PDL: event loads above may overlap the memset; stores wait for it.
    cudaGridDependencySynchronize();

    if (v0) out[idx0] = 1.0f;   // non-accumulating scatter, races benign
    if (v1) out[idx1] = 1.0f;
}

extern "C" void kernel_launch(void* const* d_in, const int* in_sizes, int n_in,
                              void* d_out, int out_size) {
    const float4* ev = (const float4*)d_in[0];
    float* out = (float*)d_out;
    int n = in_sizes[0] / 4;              // events are [N,4] float32

    // 1) zero the output (harness poisons d_out) — async memset, capturable.
    //    Measured cheaper than zero-kernel and all in-kernel zeroing schemes.
    cudaMemsetAsync(out, 0, (size_t)NUM_VOX * sizeof(float), 0);

    // 2) scatter with programmatic dependent launch.
    int blocks = (n + TPB * EV_PER_THREAD - 1) / (TPB * EV_PER_THREAD);
    cudaLaunchConfig_t cfg = {};
    cfg.gridDim  = dim3(blocks, 1, 1);
    cfg.blockDim = dim3(TPB, 1, 1);
    cfg.dynamicSmemBytes = 0;
    cfg.stream = 0;
    cudaLaunchAttribute attr[1];
    attr[0].id = cudaLaunchAttributeProgrammaticStreamSerialization;
    attr[0].val.programmaticStreamSerializationAllowed = 1;
    cfg.attrs = attr;
    cfg.numAttrs = 1;
    cudaLaunchKernelEx(&cfg, vox_scatter_kernel, ev, out, n);
}

// round 16
// speedup vs baseline: 1.9306x; 1.0003x over previous
#include <cuda_runtime.h>

// DAVIS346 voxelization constants
#define CW 346
#define CH 260
#define CC 16
#define NUM_VOX (2 * CC * CH * CW)   // 2,877,440 floats
#define EV_PER_THREAD 2
#define TPB 128

__global__ __launch_bounds__(TPB)
void vox_scatter_kernel(const float4* __restrict__ ev,
                        float* __restrict__ out, int n) {
    int base = blockIdx.x * (TPB * EV_PER_THREAD) + threadIdx.x;

    // Two independent streaming loads (MLP=2) — measured optimum across the
    // EV={1,2,4,8} sweep (covers latency without flooding the L1tex queue).
    float4 e0 = (base < n)       ? __ldcs(&ev[base])       : make_float4(0.f, 0.f, -1.f, 0.f);
    float4 e1 = (base + TPB < n) ? __ldcs(&ev[base + TPB]) : make_float4(0.f, 0.f, -1.f, 0.f);

    // idx = x + 346*y + 346*260*((ceil(16t)-1) + 16*(p>0)); exact in fp32 (<2^24)
    float fb0 = ceilf(e0.z * (float)CC) - 1.0f + ((e0.w > 0.0f) ? (float)CC : 0.0f);
    float fb1 = ceilf(e1.z * (float)CC) - 1.0f + ((e1.w > 0.0f) ? (float)CC : 0.0f);
    int idx0 = (int)fmaf((float)(CW * CH), fb0, fmaf((float)CW, e0.y, e0.x));
    int idx1 = (int)fmaf((float)(CW * CH), fb1, fmaf((float)CW, e1.y, e1.x));
    bool v0 = (e0.z > 0.0f) && (e0.z <= 1.0f);
    bool v1 = (e1.z > 0.0f) && (e1.z <= 1.0f);

    // PDL: event loads above may overlap the memset; stores wait for it.
    cudaGridDependencySynchronize();

    if (v0) out[idx0] = 1.0f;   // non-accumulating scatter, races benign
    if (v1) out[idx1] = 1.0f;
}

extern "C" void kernel_launch(void* const* d_in, const int* in_sizes, int n_in,
                              void* d_out, int out_size) {
    const float4* ev = (const float4*)d_in[0];
    float* out = (float*)d_out;
    int n = in_sizes[0] / 4;              // events are [N,4] float32

    // 1) zero the output (harness poisons d_out) — async memset, capturable.
    //    Measured cheaper than zero-kernel and all in-kernel zeroing schemes.
    cudaMemsetAsync(out, 0, (size_t)NUM_VOX * sizeof(float), 0);

    // 2) scatter with programmatic dependent launch.
    int blocks = (n + TPB * EV_PER_THREAD - 1) / (TPB * EV_PER_THREAD);
    cudaLaunchConfig_t cfg = {};
    cfg.gridDim  = dim3(blocks, 1, 1);
    cfg.blockDim = dim3(TPB, 1, 1);
    cfg.dynamicSmemBytes = 0;
    cfg.stream = 0;
    cudaLaunchAttribute attr[1];
    attr[0].id = cudaLaunchAttributeProgrammaticStreamSerialization;
    attr[0].val.programmaticStreamSerializationAllowed = 1;
    cfg.attrs = attr;
    cfg.numAttrs = 1;
    cudaLaunchKernelEx(&cfg, vox_scatter_kernel, ev, out, n);
}